// round 12
// baseline (speedup 1.0000x reference)
#include <cuda_runtime.h>
#include <cuda_fp16.h>
#include <math.h>
#include <stdint.h>

// Problem dims
#define B_  4
#define S_  1024
#define D_  1024
#define H_  512
#define N_  32
#define M_  (B_ * S_)    // 4096
#define H2_ (2 * H_)     // 1024

typedef unsigned long long u64;

// ---------------------------------------------------------------------------
// Scratch (__device__ globals; no allocs allowed)
// ---------------------------------------------------------------------------
__device__ __half g_qh[M_ * D_],  g_ql[M_ * D_];    // query split hi/lo fp16
__device__ __half g_hh[M_ * H2_], g_hl[M_ * H2_];   // GELU(h) split hi/lo fp16
__device__ __half g_w1f[D_ * H2_];                  // W1 fp16
__device__ __half g_w2f[H2_ * H_];                  // W2 fp16
__device__ float g_c[B_ * N_ * H_];
__device__ float g_m[M_ * H_];     // mixture rows

// ---------------------------------------------------------------------------
// PTX helpers
// ---------------------------------------------------------------------------
__device__ __forceinline__ uint32_t smem_u32(const void* p) {
    uint32_t a;
    asm("{ .reg .u64 t; cvta.to.shared.u64 t, %1; cvt.u32.u64 %0, t; }" : "=r"(a) : "l"(p));
    return a;
}
__device__ __forceinline__ void ldsm_x4(uint32_t& r0, uint32_t& r1, uint32_t& r2, uint32_t& r3,
                                        uint32_t addr) {
    asm volatile("ldmatrix.sync.aligned.m8n8.x4.shared.b16 {%0,%1,%2,%3}, [%4];"
                 : "=r"(r0), "=r"(r1), "=r"(r2), "=r"(r3) : "r"(addr));
}
__device__ __forceinline__ void ldsm_x4t(uint32_t& r0, uint32_t& r1, uint32_t& r2, uint32_t& r3,
                                         uint32_t addr) {
    asm volatile("ldmatrix.sync.aligned.m8n8.x4.trans.shared.b16 {%0,%1,%2,%3}, [%4];"
                 : "=r"(r0), "=r"(r1), "=r"(r2), "=r"(r3) : "r"(addr));
}
__device__ __forceinline__ void mma_f16(float* d, uint32_t a0, uint32_t a1, uint32_t a2,
                                        uint32_t a3, uint32_t b0, uint32_t b1) {
    asm volatile(
        "mma.sync.aligned.m16n8k16.row.col.f32.f16.f16.f32 "
        "{%0,%1,%2,%3}, {%4,%5,%6,%7}, {%8,%9}, {%0,%1,%2,%3};"
        : "+f"(d[0]), "+f"(d[1]), "+f"(d[2]), "+f"(d[3])
        : "r"(a0), "r"(a1), "r"(a2), "r"(a3), "r"(b0), "r"(b1));
}
__device__ __forceinline__ void cp16(uint32_t smem_addr, const void* gptr) {
    asm volatile("cp.async.cg.shared.global [%0], [%1], 16;" :: "r"(smem_addr), "l"(gptr));
}
#define CP_COMMIT() asm volatile("cp.async.commit_group;" ::: "memory")
#define CP_WAIT1()  asm volatile("cp.async.wait_group 1;" ::: "memory")
#define CP_WAIT0()  asm volatile("cp.async.wait_group 0;" ::: "memory")

__device__ __forceinline__ u64 f2fma(u64 d, u64 a, u64 b) {
    asm("fma.rn.f32x2 %0, %1, %2, %0;" : "+l"(d) : "l"(a), "l"(b));
    return d;
}
__device__ __forceinline__ u64 dup2(float x) {
    u64 r;
    asm("mov.b64 %0, {%1, %1};" : "=l"(r) : "f"(x));
    return r;
}
__device__ __forceinline__ void unpack2(u64 v, float& lo, float& hi) {
    asm("mov.b64 {%0, %1}, %2;" : "=f"(lo), "=f"(hi) : "l"(v));
}

// ---------------------------------------------------------------------------
// Merged prep: query hi/lo split + W1/W2 convert + compute_c, one launch.
// Blocks [0,4096): query split; [4096,5120): W1; [5120,5632): W2;
// [5632,5760): compute_c (one (b,n) row each; threads t<128 active).
// ---------------------------------------------------------------------------
__global__ void prep_convert(const float* __restrict__ q,
                             const float* __restrict__ W1,
                             const float* __restrict__ W2,
                             const float* __restrict__ hcm,
                             const float* __restrict__ Wa,
                             __half* __restrict__ qh, __half* __restrict__ ql,
                             __half* __restrict__ w1f, __half* __restrict__ w2f,
                             float* __restrict__ c) {
    const int bid = blockIdx.x;
    const int t = threadIdx.x;
    if (bid < 4096) {
        int i = bid * 256 + t;
        float4 v = ((const float4*)q)[i];
        float vv[4] = {v.x, v.y, v.z, v.w};
        uint32_t hh[4], ll[4];
#pragma unroll
        for (int k = 0; k < 4; k++) {
            __half h = __float2half_rn(vv[k]);
            __half l = __float2half_rn(vv[k] - __half2float(h));
            hh[k] = __half_as_ushort(h);
            ll[k] = __half_as_ushort(l);
        }
        uint2 ph, pl;
        ph.x = hh[0] | (hh[1] << 16); ph.y = hh[2] | (hh[3] << 16);
        pl.x = ll[0] | (ll[1] << 16); pl.y = ll[2] | (ll[3] << 16);
        ((uint2*)qh)[i] = ph;
        ((uint2*)ql)[i] = pl;
    } else if (bid < 5632) {
        const float* src = (bid < 5120) ? W1 : W2;
        __half* dst = (bid < 5120) ? w1f : w2f;
        int i = (bid < 5120) ? (bid - 4096) * 256 + t : (bid - 5120) * 256 + t;
        float4 v = ((const float4*)src)[i];
        float vv[4] = {v.x, v.y, v.z, v.w};
        uint32_t hh[4];
#pragma unroll
        for (int k = 0; k < 4; k++) hh[k] = __half_as_ushort(__float2half_rn(vv[k]));
        uint2 ph;
        ph.x = hh[0] | (hh[1] << 16); ph.y = hh[2] | (hh[3] << 16);
        ((uint2*)dst)[i] = ph;
    } else {
        // compute_c for bn = bid - 5632; only threads t<128 do work.
        __shared__ __align__(16) float hs[1024];
        __shared__ __align__(16) float was[512];
        const int bn = bid - 5632;
        if (t < 128) {
#pragma unroll
            for (int r = 0; r < 4; r++) {
                int j = t + 128 * r;
                float v = hcm[(size_t)bn * H_ + j];
                hs[j] = v; hs[j + 512] = v;
                was[j] = Wa[j];
            }
        }
        __syncthreads();
        if (t < 128) {
            const int h0 = 4 * t;
            float4 a = {0.f, 0.f, 0.f, 0.f};
            float4 mw = *(const float4*)&hs[h0];
#pragma unroll 4
            for (int i = 0; i < 512; i += 4) {
                float4 kv = *(const float4*)&was[i];
                float4 mn = *(const float4*)&hs[i + 4 + h0];
                a.x = fmaf(kv.x, mw.x, a.x); a.y = fmaf(kv.x, mw.y, a.y); a.z = fmaf(kv.x, mw.z, a.z); a.w = fmaf(kv.x, mw.w, a.w);
                a.x = fmaf(kv.y, mw.y, a.x); a.y = fmaf(kv.y, mw.z, a.y); a.z = fmaf(kv.y, mw.w, a.z); a.w = fmaf(kv.y, mn.x, a.w);
                a.x = fmaf(kv.z, mw.z, a.x); a.y = fmaf(kv.z, mw.w, a.y); a.z = fmaf(kv.z, mn.x, a.z); a.w = fmaf(kv.z, mn.y, a.w);
                a.x = fmaf(kv.w, mw.w, a.x); a.y = fmaf(kv.w, mn.x, a.y); a.z = fmaf(kv.w, mn.y, a.z); a.w = fmaf(kv.w, mn.z, a.w);
                mw = mn;
            }
            *(float4*)&c[(size_t)bn * H_ + h0] = a;
        }
    }
}

// ---------------------------------------------------------------------------
// GEMM1 (fp16 2-term A-split), 128x128 tile, 2-stage cp.async, 96KB, 2 CTAs/SM.
// GELU(acc+bias) -> split fp16 (outH/outL).
// ---------------------------------------------------------------------------
__global__ void __launch_bounds__(256, 2)
gemm_mma1(const __half* __restrict__ Ah, const __half* __restrict__ Al,
          const __half* __restrict__ Bf,
          const float* __restrict__ bias,
          __half* __restrict__ outH, __half* __restrict__ outL,
          int Ntot, int Ktot) {
    extern __shared__ char smp[];
    const uint32_t sb = smem_u32(smp);
    const int tid = threadIdx.x;
    const int wid = tid >> 5, lane = tid & 31;
    const int wm = wid >> 2, wn = wid & 3;
    const int m_warp = wm * 64, n_warp = wn * 32;
    const int m0 = blockIdx.y * 128, n0 = blockIdx.x * 128;
    const int gid = lane >> 2, tig = lane & 3;
    const uint32_t STG = 49152;

    auto load_stage = [&](int c, int buf) {
        const uint32_t bb = sb + (uint32_t)buf * STG;
        const int k0 = c * 64;
#pragma unroll
        for (int j = 0; j < 4; j++) {
            int g = tid + 256 * j;
            int r = g >> 3, u = g & 7;
            size_t so = (size_t)(m0 + r) * Ktot + k0 + u * 8;
            uint32_t sw = (uint32_t)(r * 128 + ((u ^ (r & 7)) << 4));
            cp16(bb + sw, Ah + so);
            cp16(bb + 16384 + sw, Al + so);
        }
#pragma unroll
        for (int j = 0; j < 4; j++) {
            int g = tid + 256 * j;
            int r = g >> 4, u = g & 15;
            size_t so = (size_t)(k0 + r) * Ntot + n0 + u * 8;
            uint32_t sw = (uint32_t)(r * 256 + (((u & 8) | ((u ^ r) & 7)) << 4));
            cp16(bb + 32768 + sw, Bf + so);
        }
    };

    float acc[4][4][4] = {};
    const int NK = Ktot / 64;
    load_stage(0, 0);
    CP_COMMIT();

    for (int c = 0; c < NK; c++) {
        if (c + 1 < NK) { load_stage(c + 1, (c + 1) & 1); CP_COMMIT(); CP_WAIT1(); }
        else           { CP_WAIT0(); }
        __syncthreads();

        const uint32_t bb = sb + (uint32_t)(c & 1) * STG;
#pragma unroll
        for (int s = 0; s < 4; s++) {
            uint32_t bfr[2][4];
            {
                const int kr = s * 16 + (lane & 7) + (lane & 8);
                const uint32_t swk = (uint32_t)(kr * 256);
#pragma unroll
                for (int nt = 0; nt < 2; nt++) {
                    int un = (n_warp >> 3) + nt * 2 + (lane >> 4);
                    uint32_t sw = swk + (uint32_t)((((un & 8) | ((un ^ kr) & 7)) << 4));
                    ldsm_x4t(bfr[nt][0], bfr[nt][1], bfr[nt][2], bfr[nt][3], bb + 32768 + sw);
                }
            }
            const int ar = m_warp + (lane & 15);
            const int au = s * 2 + (lane >> 4);
            uint32_t afA[8], afB[8];
            {
                const int r = ar;
                uint32_t sw = (uint32_t)(r * 128 + ((au ^ (r & 7)) << 4));
                ldsm_x4(afA[0], afA[1], afA[2], afA[3], bb + sw);
                ldsm_x4(afA[4], afA[5], afA[6], afA[7], bb + 16384 + sw);
            }
#pragma unroll
            for (int mt = 0; mt < 4; mt++) {
                uint32_t* cur = (mt & 1) ? afB : afA;
                uint32_t* nxt = (mt & 1) ? afA : afB;
                if (mt < 3) {
                    const int r = ar + (mt + 1) * 16;
                    uint32_t sw = (uint32_t)(r * 128 + ((au ^ (r & 7)) << 4));
                    ldsm_x4(nxt[0], nxt[1], nxt[2], nxt[3], bb + sw);
                    ldsm_x4(nxt[4], nxt[5], nxt[6], nxt[7], bb + 16384 + sw);
                }
#pragma unroll
                for (int nb = 0; nb < 4; nb++) {
                    const int nt = nb >> 1, hf = (nb & 1) * 2;
                    mma_f16(acc[mt][nb], cur[0], cur[1], cur[2], cur[3], bfr[nt][hf], bfr[nt][hf + 1]);
                    mma_f16(acc[mt][nb], cur[4], cur[5], cur[6], cur[7], bfr[nt][hf], bfr[nt][hf + 1]);
                }
            }
        }
        __syncthreads();
    }

#pragma unroll
    for (int mt = 0; mt < 4; mt++) {
        const int r0 = m0 + m_warp + mt * 16 + gid;
#pragma unroll
        for (int j = 0; j < 4; j++) {
            const int col = n0 + n_warp + j * 8 + tig * 2;
            float2 bv = *(const float2*)&bias[col];
            float v[4];
            v[0] = acc[mt][j][0] + bv.x; v[1] = acc[mt][j][1] + bv.y;
            v[2] = acc[mt][j][2] + bv.x; v[3] = acc[mt][j][3] + bv.y;
#pragma unroll
            for (int q = 0; q < 4; q++)
                v[q] = 0.5f * v[q] * (1.0f + erff(v[q] * 0.70710678118654752f));
#pragma unroll
            for (int hp = 0; hp < 2; hp++) {
                const int rr = r0 + hp * 8;
                float a = v[hp * 2], b = v[hp * 2 + 1];
                __half h0 = __float2half_rn(a);
                __half h1 = __float2half_rn(b);
                __half l0 = __float2half_rn(a - __half2float(h0));
                __half l1 = __float2half_rn(b - __half2float(h1));
                uint32_t ph = (uint32_t)__half_as_ushort(h0) | ((uint32_t)__half_as_ushort(h1) << 16);
                uint32_t pl = (uint32_t)__half_as_ushort(l0) | ((uint32_t)__half_as_ushort(l1) << 16);
                *(uint32_t*)(outH + (size_t)rr * Ntot + col) = ph;
                *(uint32_t*)(outL + (size_t)rr * Ntot + col) = pl;
            }
        }
    }
}

// ---------------------------------------------------------------------------
// GEMM2 (fp16 2-term A-split), 64x128 tile -> grid 256 = 2 CTAs/SM.
// stage (32KB): Ah[64][64] +0 | Al +8K | Bf[64][128] +16K. acc+bias -> fp32.
// ---------------------------------------------------------------------------
__global__ void __launch_bounds__(256, 2)
gemm_mma2(const __half* __restrict__ Ah, const __half* __restrict__ Al,
          const __half* __restrict__ Bf,
          const float* __restrict__ bias,
          float* __restrict__ outF,
          int Ntot, int Ktot) {
    extern __shared__ char smp[];
    const uint32_t sb = smem_u32(smp);
    const int tid = threadIdx.x;
    const int wid = tid >> 5, lane = tid & 31;
    const int wm = wid >> 2, wn = wid & 3;
    const int m_warp = wm * 32, n_warp = wn * 32;
    const int m0 = blockIdx.y * 64, n0 = blockIdx.x * 128;
    const int gid = lane >> 2, tig = lane & 3;
    const uint32_t STG = 32768;

    auto load_stage = [&](int c, int buf) {
        const uint32_t bb = sb + (uint32_t)buf * STG;
        const int k0 = c * 64;
#pragma unroll
        for (int j = 0; j < 2; j++) {          // A: 64 rows x 8 units, hi+lo
            int g = tid + 256 * j;
            int r = g >> 3, u = g & 7;
            size_t so = (size_t)(m0 + r) * Ktot + k0 + u * 8;
            uint32_t sw = (uint32_t)(r * 128 + ((u ^ (r & 7)) << 4));
            cp16(bb + sw, Ah + so);
            cp16(bb + 8192 + sw, Al + so);
        }
#pragma unroll
        for (int j = 0; j < 4; j++) {          // B: 64 rows x 16 units
            int g = tid + 256 * j;
            int r = g >> 4, u = g & 15;
            size_t so = (size_t)(k0 + r) * Ntot + n0 + u * 8;
            uint32_t sw = (uint32_t)(r * 256 + (((u & 8) | ((u ^ r) & 7)) << 4));
            cp16(bb + 16384 + sw, Bf + so);
        }
    };

    float acc[2][4][4] = {};
    const int NK = Ktot / 64;
    load_stage(0, 0);
    CP_COMMIT();

    for (int c = 0; c < NK; c++) {
        if (c + 1 < NK) { load_stage(c + 1, (c + 1) & 1); CP_COMMIT(); CP_WAIT1(); }
        else           { CP_WAIT0(); }
        __syncthreads();

        const uint32_t bb = sb + (uint32_t)(c & 1) * STG;
#pragma unroll
        for (int s = 0; s < 4; s++) {
            uint32_t bfr[2][4];
            {
                const int kr = s * 16 + (lane & 7) + (lane & 8);
                const uint32_t swk = (uint32_t)(kr * 256);
#pragma unroll
                for (int nt = 0; nt < 2; nt++) {
                    int un = (n_warp >> 3) + nt * 2 + (lane >> 4);
                    uint32_t sw = swk + (uint32_t)((((un & 8) | ((un ^ kr) & 7)) << 4));
                    ldsm_x4t(bfr[nt][0], bfr[nt][1], bfr[nt][2], bfr[nt][3], bb + 16384 + sw);
                }
            }
            const int ar = m_warp + (lane & 15);
            const int au = s * 2 + (lane >> 4);
            uint32_t afA[8], afB[8];
            {
                const int r = ar;
                uint32_t sw = (uint32_t)(r * 128 + ((au ^ (r & 7)) << 4));
                ldsm_x4(afA[0], afA[1], afA[2], afA[3], bb + sw);
                ldsm_x4(afA[4], afA[5], afA[6], afA[7], bb + 8192 + sw);
            }
#pragma unroll
            for (int mt = 0; mt < 2; mt++) {
                uint32_t* cur = (mt & 1) ? afB : afA;
                uint32_t* nxt = (mt & 1) ? afA : afB;
                if (mt < 1) {
                    const int r = ar + 16;
                    uint32_t sw = (uint32_t)(r * 128 + ((au ^ (r & 7)) << 4));
                    ldsm_x4(nxt[0], nxt[1], nxt[2], nxt[3], bb + sw);
                    ldsm_x4(nxt[4], nxt[5], nxt[6], nxt[7], bb + 8192 + sw);
                }
#pragma unroll
                for (int nb = 0; nb < 4; nb++) {
                    const int nt = nb >> 1, hf = (nb & 1) * 2;
                    mma_f16(acc[mt][nb], cur[0], cur[1], cur[2], cur[3], bfr[nt][hf], bfr[nt][hf + 1]);
                    mma_f16(acc[mt][nb], cur[4], cur[5], cur[6], cur[7], bfr[nt][hf], bfr[nt][hf + 1]);
                }
            }
        }
        __syncthreads();
    }

#pragma unroll
    for (int mt = 0; mt < 2; mt++) {
        const int r0 = m0 + m_warp + mt * 16 + gid;
#pragma unroll
        for (int j = 0; j < 4; j++) {
            const int col = n0 + n_warp + j * 8 + tig * 2;
            float2 bv = *(const float2*)&bias[col];
            *(float2*)(outF + (size_t)r0 * Ntot + col) =
                make_float2(acc[mt][j][0] + bv.x, acc[mt][j][1] + bv.y);
            *(float2*)(outF + (size_t)(r0 + 8) * Ntot + col) =
                make_float2(acc[mt][j][2] + bv.x, acc[mt][j][3] + bv.y);
        }
    }
}

// ---------------------------------------------------------------------------
// Fused S+M: normalize keys + scores + softmax + mixture -> m[4096,512]
// ---------------------------------------------------------------------------
__global__ void __launch_bounds__(256)
score_mix(float* __restrict__ keys, const float* __restrict__ c,
          const float* __restrict__ hcm, float* __restrict__ m) {
    extern __shared__ __align__(16) float sm[];
    float* cs = sm;
    float* ks = sm + 16512;
    float* sc = sm + 33024;
    float* ws = sm + 34080;
    const int blk = blockIdx.x;
    const int row0 = blk * 32;
    const int b = row0 >> 10;
    const int t = threadIdx.x;
    const int lane = t & 31, wid = t >> 5;

    {
        const float4* cg = (const float4*)(c + (size_t)b * N_ * H_);
        for (int j = t; j < 32 * 128; j += 256) {
            int r = j >> 7, u = j & 127;
            *(float4*)&cs[r * 516 + 4 * u] = cg[j];
        }
    }
#pragma unroll
    for (int rr = 0; rr < 4; rr++) {
        const int r = wid * 4 + rr;
        float4* kg = (float4*)(keys + (size_t)(row0 + r) * H_);
        float4 kv[4];
        float ss = 0.f;
#pragma unroll
        for (int u = 0; u < 4; u++) {
            kv[u] = kg[u * 32 + lane];
            ss += kv[u].x * kv[u].x + kv[u].y * kv[u].y + kv[u].z * kv[u].z + kv[u].w * kv[u].w;
        }
#pragma unroll
        for (int o = 16; o; o >>= 1) ss += __shfl_xor_sync(0xffffffffu, ss, o);
        const float inv = 1.0f / fmaxf(sqrtf(ss), 1e-12f);
#pragma unroll
        for (int u = 0; u < 4; u++) {
            kv[u].x *= inv; kv[u].y *= inv; kv[u].z *= inv; kv[u].w *= inv;
            kg[u * 32 + lane] = kv[u];
            *(float4*)&ks[r * 516 + 4 * (u * 32 + lane)] = kv[u];
        }
    }
    __syncthreads();

    {
        const int r = t >> 3, l = t & 7;
        const float* ksr = ks + r * 516;
        const float* c0p = cs + l * 516;
        const float* c1p = cs + (l + 8) * 516;
        const float* c2p = cs + (l + 16) * 516;
        const float* c3p = cs + (l + 24) * 516;
        float p0 = 0.f, p1 = 0.f, p2 = 0.f, p3 = 0.f;
#pragma unroll 4
        for (int i = 0; i < 512; i += 4) {
            float4 kv = *(const float4*)(ksr + i);
            float4 a0 = *(const float4*)(c0p + i);
            float4 a1 = *(const float4*)(c1p + i);
            float4 a2 = *(const float4*)(c2p + i);
            float4 a3 = *(const float4*)(c3p + i);
            p0 += kv.x * a0.x + kv.y * a0.y + kv.z * a0.z + kv.w * a0.w;
            p1 += kv.x * a1.x + kv.y * a1.y + kv.z * a1.z + kv.w * a1.w;
            p2 += kv.x * a2.x + kv.y * a2.y + kv.z * a2.z + kv.w * a2.w;
            p3 += kv.x * a3.x + kv.y * a3.y + kv.z * a3.z + kv.w * a3.w;
        }
        sc[r * 33 + l] = p0;
        sc[r * 33 + l + 8] = p1;
        sc[r * 33 + l + 16] = p2;
        sc[r * 33 + l + 24] = p3;
    }
    __syncthreads();

    {
        const float4* hg = (const float4*)(hcm + (size_t)b * N_ * H_);
        float4* h4 = (float4*)cs;
        for (int j = t; j < 32 * 128; j += 256) h4[j] = hg[j];
    }
    if (t < 32) {
        float v[32];
        float mx = -1e30f;
#pragma unroll
        for (int n = 0; n < 32; n++) { v[n] = sc[t * 33 + n]; mx = fmaxf(mx, v[n]); }
        float s = 0.f;
#pragma unroll
        for (int n = 0; n < 32; n++) { v[n] = expf(v[n] - mx); s += v[n]; }
        const float is = 1.0f / s;
#pragma unroll
        for (int n = 0; n < 32; n++) ws[t * 33 + n] = v[n] * is;
    }
    __syncthreads();

    {
        const int seg = t >> 5;
        u64 acc[32];
#pragma unroll
        for (int q = 0; q < 32; q++) acc[q] = 0;
        const u64* hp = (const u64*)cs;
#pragma unroll 4
        for (int n = 0; n < 32; n++) {
            u64 w2 = dup2(ws[lane * 33 + n]);
            const ulonglong2* h2 = (const ulonglong2*)(hp + n * 256 + seg * 32);
#pragma unroll
            for (int q = 0; q < 16; q++) {
                ulonglong2 hv = h2[q];
                acc[2 * q] = f2fma(acc[2 * q], w2, hv.x);
                acc[2 * q + 1] = f2fma(acc[2 * q + 1], w2, hv.y);
            }
        }
        u64* mr = (u64*)(m + (size_t)(row0 + lane) * H_ + seg * 64);
#pragma unroll
        for (int q = 0; q < 32; q++) mr[q] = acc[q];
    }
}

// ---------------------------------------------------------------------------
// Kernel C: circular correlation via FFMA2, 8 outputs/thread, swizzled mm2.
// ---------------------------------------------------------------------------
__device__ __forceinline__ void mm_store(float* base, int x, int comp, float v) {
    int p = x >> 1;
    int q = p ^ ((p >> 3) & 7);
    base[q * 4 + (x & 1) * 2 + comp] = v;
}

__global__ void __launch_bounds__(128)
correlate_kernel(const float* __restrict__ keys, const float* __restrict__ m,
                 float* __restrict__ context) {
    __shared__ __align__(16) float k2f[2][512];
    __shared__ __align__(16) float mmf[2][1536];
    const int t = threadIdx.x;
    const int rr = t >> 6, tt = t & 63;
    const int row = blockIdx.x * 2 + rr;

    float* k2r = k2f[rr];
    float* mmr = mmf[rr];
    {
        const float4* kg = (const float4*)(keys + (size_t)row * H_);
        const float4* mg = (const float4*)(m + (size_t)row * H_);
#pragma unroll
        for (int e = 0; e < 2; e++) {
            int j4 = 2 * tt + e;
            float4 kv = kg[j4];
            float4 mv = mg[j4];
            float kvv[4] = {kv.x, kv.y, kv.z, kv.w};
            float mvv[4] = {mv.x, mv.y, mv.z, mv.w};
#pragma unroll
            for (int q = 0; q < 4; q++) {
                int j = 4 * j4 + q;
                if (j < 256) k2r[2 * j] = kvv[q];
                else         k2r[2 * (j - 256) + 1] = kvv[q];
                mm_store(mmr, j, 0, mvv[q]);
                mm_store(mmr, j + 256, 1, mvv[q]);
                if (j < 256) mm_store(mmr, j + 512, 0, mvv[q]);
                else         mm_store(mmr, j - 256, 1, mvv[q]);
            }
        }
    }
    __syncthreads();

    const u64* mp64 = (const u64*)mmr;
    const ulonglong2* kp = (const ulonglong2*)k2r;
    u64 A[8];
    u64 w[8];
#pragma unroll
    for (int q = 0; q < 8; q++) A[q] = 0;
#pragma unroll
    for (int e = 0; e < 4; e++) {
        int u = 4 * tt + e;
        int q = u ^ ((u >> 3) & 7);
        ulonglong2 xv = *(const ulonglong2*)(mp64 + 2 * q);
        w[2 * e] = xv.x; w[2 * e + 1] = xv.y;
    }

#pragma unroll 8
    for (int n = 0; n < 64; n++) {
        ulonglong2 ka = kp[2 * n];
        ulonglong2 kb = kp[2 * n + 1];
        int ua = 4 * tt + 2 * n + 4;
        int ub = ua + 1;
        int pa = ua ^ ((ua >> 3) & 7);
        int pb = ub ^ ((ub >> 3) & 7);
        ulonglong2 xa = *(const ulonglong2*)(mp64 + 2 * pa);
        ulonglong2 xb = *(const ulonglong2*)(mp64 + 2 * pb);
        u64 W8 = xa.x, W9 = xa.y, W10 = xb.x, W11 = xb.y;
        A[0] = f2fma(A[0], ka.x, w[0]); A[1] = f2fma(A[1], ka.x, w[1]);
        A[2] = f2fma(A[2], ka.x, w[2]); A[3] = f2fma(A[3], ka.x, w[3]);
        A[4] = f2fma(A[4], ka.x, w[4]); A[5] = f2fma(A[5], ka.x, w[5]);
        A[6] = f2fma(A[6], ka.x, w[6]); A[7] = f2fma(A[7], ka.x, w[7]);
        A[0] = f2fma(A[0], ka.y, w[1]); A[1] = f2fma(A[1], ka.y, w[2]);
        A[2] = f2fma(A[2], ka.y, w[3]); A[3] = f2fma(A[3], ka.y, w[4]);
        A[4] = f2fma(A[4], ka.y, w[5]); A[5] = f2fma(A[5], ka.y, w[6]);
        A[6] = f2fma(A[6], ka.y, w[7]); A[7] = f2fma(A[7], ka.y, W8);
        A[0] = f2fma(A[0], kb.x, w[2]); A[1] = f2fma(A[1], kb.x, w[3]);
        A[2] = f2fma(A[2], kb.x, w[4]); A[3] = f2fma(A[3], kb.x, w[5]);
        A[4] = f2fma(A[4], kb.x, w[6]); A[5] = f2fma(A[5], kb.x, w[7]);
        A[6] = f2fma(A[6], kb.x, W8);   A[7] = f2fma(A[7], kb.x, W9);
        A[0] = f2fma(A[0], kb.y, w[3]); A[1] = f2fma(A[1], kb.y, w[4]);
        A[2] = f2fma(A[2], kb.y, w[5]); A[3] = f2fma(A[3], kb.y, w[6]);
        A[4] = f2fma(A[4], kb.y, w[7]); A[5] = f2fma(A[5], kb.y, W8);
        A[6] = f2fma(A[6], kb.y, W9);   A[7] = f2fma(A[7], kb.y, W10);
        w[0] = w[4]; w[1] = w[5]; w[2] = w[6]; w[3] = w[7];
        w[4] = W8; w[5] = W9; w[6] = W10; w[7] = W11;
    }

    float o[8];
#pragma unroll
    for (int q = 0; q < 8; q++) {
        float lo, hi;
        unpack2(A[q], lo, hi);
        o[q] = lo + hi;
    }
    float* op = context + (size_t)row * H_ + 8 * tt;
    *(float4*)op = make_float4(o[0], o[1], o[2], o[3]);
    *(float4*)(op + 4) = make_float4(o[4], o[5], o[6], o[7]);
}

// ---------------------------------------------------------------------------
// Launch
// ---------------------------------------------------------------------------
extern "C" void kernel_launch(void* const* d_in, const int* in_sizes, int n_in,
                              void* d_out, int out_size) {
    const float* query = (const float*)d_in[0];
    const float* hcm   = (const float*)d_in[1];
    const float* W1    = (const float*)d_in[2];
    const float* b1    = (const float*)d_in[3];
    const float* W2    = (const float*)d_in[4];
    const float* b2    = (const float*)d_in[5];
    const float* Wa    = (const float*)d_in[6];
    // ba unused: softmax is shift-invariant

    float* out = (float*)d_out;
    float* context = out;
    float* keys    = out + (size_t)M_ * H_;

    __half *qh, *ql, *hh, *hl, *w1f, *w2f;
    float *cbuf, *mbuf;
    cudaGetSymbolAddress((void**)&qh, g_qh);
    cudaGetSymbolAddress((void**)&ql, g_ql);
    cudaGetSymbolAddress((void**)&hh, g_hh);
    cudaGetSymbolAddress((void**)&hl, g_hl);
    cudaGetSymbolAddress((void**)&w1f, g_w1f);
    cudaGetSymbolAddress((void**)&w2f, g_w2f);
    cudaGetSymbolAddress((void**)&cbuf, g_c);
    cudaGetSymbolAddress((void**)&mbuf, g_m);

    const int G1_SMEM = 2 * 49152;                             // 96 KB
    const int G2_SMEM = 2 * 32768;                             // 64 KB
    const int SM_SMEM = (2 * 32 * 516 + 2 * 32 * 33) * 4;      // 140544
    cudaFuncSetAttribute(gemm_mma1, cudaFuncAttributeMaxDynamicSharedMemorySize, G1_SMEM);
    cudaFuncSetAttribute(gemm_mma2, cudaFuncAttributeMaxDynamicSharedMemorySize, G2_SMEM);
    cudaFuncSetAttribute(score_mix, cudaFuncAttributeMaxDynamicSharedMemorySize, SM_SMEM);

    prep_convert<<<5760, 256>>>(query, W1, W2, hcm, Wa, qh, ql, w1f, w2f, cbuf);

    gemm_mma1<<<dim3(H2_ / 128, M_ / 128), 256, G1_SMEM>>>(
        qh, ql, w1f, b1, hh, hl, H2_, D_);
    gemm_mma2<<<dim3(H_ / 128, M_ / 64), 256, G2_SMEM>>>(
        hh, hl, w2f, b2, keys, H_, H2_);

    score_mix<<<M_ / 32, 256, SM_SMEM>>>(keys, cbuf, hcm, mbuf);
    correlate_kernel<<<M_ / 2, 128>>>(keys, mbuf, context);
}

// round 14
// speedup vs baseline: 1.0493x; 1.0493x over previous
#include <cuda_runtime.h>
#include <cuda_fp16.h>
#include <math.h>
#include <stdint.h>

// Problem dims
#define B_  4
#define S_  1024
#define D_  1024
#define H_  512
#define N_  32
#define M_  (B_ * S_)    // 4096
#define H2_ (2 * H_)     // 1024

typedef unsigned long long u64;

// ---------------------------------------------------------------------------
// Scratch (__device__ globals; no allocs allowed)
// ---------------------------------------------------------------------------
__device__ __half g_qh[M_ * D_],  g_ql[M_ * D_];    // query split hi/lo fp16
__device__ __half g_hh[M_ * H2_], g_hl[M_ * H2_];   // GELU(h) split hi/lo fp16
__device__ __half g_w1f[D_ * H2_];                  // W1 fp16
__device__ __half g_w2f[H2_ * H_];                  // W2 fp16
__device__ float g_c[B_ * N_ * H_];
__device__ float g_w[M_ * N_];     // softmax weights
__device__ float g_m[M_ * H_];     // mixture rows

// ---------------------------------------------------------------------------
// PTX helpers
// ---------------------------------------------------------------------------
__device__ __forceinline__ uint32_t smem_u32(const void* p) {
    uint32_t a;
    asm("{ .reg .u64 t; cvta.to.shared.u64 t, %1; cvt.u32.u64 %0, t; }" : "=r"(a) : "l"(p));
    return a;
}
__device__ __forceinline__ void ldsm_x4(uint32_t& r0, uint32_t& r1, uint32_t& r2, uint32_t& r3,
                                        uint32_t addr) {
    asm volatile("ldmatrix.sync.aligned.m8n8.x4.shared.b16 {%0,%1,%2,%3}, [%4];"
                 : "=r"(r0), "=r"(r1), "=r"(r2), "=r"(r3) : "r"(addr));
}
__device__ __forceinline__ void ldsm_x4t(uint32_t& r0, uint32_t& r1, uint32_t& r2, uint32_t& r3,
                                         uint32_t addr) {
    asm volatile("ldmatrix.sync.aligned.m8n8.x4.trans.shared.b16 {%0,%1,%2,%3}, [%4];"
                 : "=r"(r0), "=r"(r1), "=r"(r2), "=r"(r3) : "r"(addr));
}
__device__ __forceinline__ void mma_f16(float* d, uint32_t a0, uint32_t a1, uint32_t a2,
                                        uint32_t a3, uint32_t b0, uint32_t b1) {
    asm volatile(
        "mma.sync.aligned.m16n8k16.row.col.f32.f16.f16.f32 "
        "{%0,%1,%2,%3}, {%4,%5,%6,%7}, {%8,%9}, {%0,%1,%2,%3};"
        : "+f"(d[0]), "+f"(d[1]), "+f"(d[2]), "+f"(d[3])
        : "r"(a0), "r"(a1), "r"(a2), "r"(a3), "r"(b0), "r"(b1));
}
__device__ __forceinline__ void cp16(uint32_t smem_addr, const void* gptr) {
    asm volatile("cp.async.cg.shared.global [%0], [%1], 16;" :: "r"(smem_addr), "l"(gptr));
}
#define CP_COMMIT() asm volatile("cp.async.commit_group;" ::: "memory")
#define CP_WAIT1()  asm volatile("cp.async.wait_group 1;" ::: "memory")
#define CP_WAIT0()  asm volatile("cp.async.wait_group 0;" ::: "memory")

__device__ __forceinline__ u64 f2fma(u64 d, u64 a, u64 b) {
    asm("fma.rn.f32x2 %0, %1, %2, %0;" : "+l"(d) : "l"(a), "l"(b));
    return d;
}
__device__ __forceinline__ u64 dup2(float x) {
    u64 r;
    asm("mov.b64 %0, {%1, %1};" : "=l"(r) : "f"(x));
    return r;
}
__device__ __forceinline__ void unpack2(u64 v, float& lo, float& hi) {
    asm("mov.b64 {%0, %1}, %2;" : "=f"(lo), "=f"(hi) : "l"(v));
}

// ---------------------------------------------------------------------------
// Merged prep: query hi/lo split + W1/W2 fp16 convert.
// Blocks [0,4096): query; [4096,5120): W1; [5120,5632): W2.
// ---------------------------------------------------------------------------
__global__ void prep_convert(const float* __restrict__ q,
                             const float* __restrict__ W1,
                             const float* __restrict__ W2,
                             __half* __restrict__ qh, __half* __restrict__ ql,
                             __half* __restrict__ w1f, __half* __restrict__ w2f) {
    const int bid = blockIdx.x;
    const int t = threadIdx.x;
    if (bid < 4096) {
        int i = bid * 256 + t;
        float4 v = ((const float4*)q)[i];
        float vv[4] = {v.x, v.y, v.z, v.w};
        uint32_t hh[4], ll[4];
#pragma unroll
        for (int k = 0; k < 4; k++) {
            __half h = __float2half_rn(vv[k]);
            __half l = __float2half_rn(vv[k] - __half2float(h));
            hh[k] = __half_as_ushort(h);
            ll[k] = __half_as_ushort(l);
        }
        uint2 ph, pl;
        ph.x = hh[0] | (hh[1] << 16); ph.y = hh[2] | (hh[3] << 16);
        pl.x = ll[0] | (ll[1] << 16); pl.y = ll[2] | (ll[3] << 16);
        ((uint2*)qh)[i] = ph;
        ((uint2*)ql)[i] = pl;
    } else {
        const float* src = (bid < 5120) ? W1 : W2;
        __half* dst = (bid < 5120) ? w1f : w2f;
        int i = (bid < 5120) ? (bid - 4096) * 256 + t : (bid - 5120) * 256 + t;
        float4 v = ((const float4*)src)[i];
        float vv[4] = {v.x, v.y, v.z, v.w};
        uint32_t hh[4];
#pragma unroll
        for (int k = 0; k < 4; k++) hh[k] = __half_as_ushort(__float2half_rn(vv[k]));
        uint2 ph;
        ph.x = hh[0] | (hh[1] << 16); ph.y = hh[2] | (hh[3] << 16);
        ((uint2*)dst)[i] = ph;
    }
}

// ---------------------------------------------------------------------------
// Tensor-core GEMM (round-11 proven: fp16 2-term, 128x128, 96KB, 2 CTAs/SM,
// mt-level A-fragment double buffering).
// ---------------------------------------------------------------------------
template <int MODE>
__global__ void __launch_bounds__(256, 2)
gemm_mma(const __half* __restrict__ Ah, const __half* __restrict__ Al,
         const __half* __restrict__ Bf,
         const float* __restrict__ bias,
         float* __restrict__ outF,
         __half* __restrict__ outH, __half* __restrict__ outL,
         int Ntot, int Ktot) {
    extern __shared__ char smp[];
    const uint32_t sb = smem_u32(smp);
    const int tid = threadIdx.x;
    const int wid = tid >> 5, lane = tid & 31;
    const int wm = wid >> 2, wn = wid & 3;
    const int m_warp = wm * 64, n_warp = wn * 32;
    const int m0 = blockIdx.y * 128, n0 = blockIdx.x * 128;
    const int gid = lane >> 2, tig = lane & 3;
    const uint32_t STG = 49152;

    auto load_stage = [&](int c, int buf) {
        const uint32_t bb = sb + (uint32_t)buf * STG;
        const int k0 = c * 64;
#pragma unroll
        for (int j = 0; j < 4; j++) {
            int g = tid + 256 * j;
            int r = g >> 3, u = g & 7;
            size_t so = (size_t)(m0 + r) * Ktot + k0 + u * 8;
            uint32_t sw = (uint32_t)(r * 128 + ((u ^ (r & 7)) << 4));
            cp16(bb + sw, Ah + so);
            cp16(bb + 16384 + sw, Al + so);
        }
#pragma unroll
        for (int j = 0; j < 4; j++) {
            int g = tid + 256 * j;
            int r = g >> 4, u = g & 15;
            size_t so = (size_t)(k0 + r) * Ntot + n0 + u * 8;
            uint32_t sw = (uint32_t)(r * 256 + (((u & 8) | ((u ^ r) & 7)) << 4));
            cp16(bb + 32768 + sw, Bf + so);
        }
    };

    float acc[4][4][4] = {};
    const int NK = Ktot / 64;
    load_stage(0, 0);
    CP_COMMIT();

    for (int c = 0; c < NK; c++) {
        if (c + 1 < NK) { load_stage(c + 1, (c + 1) & 1); CP_COMMIT(); CP_WAIT1(); }
        else           { CP_WAIT0(); }
        __syncthreads();

        const uint32_t bb = sb + (uint32_t)(c & 1) * STG;
#pragma unroll
        for (int s = 0; s < 4; s++) {
            uint32_t bfr[2][4];
            {
                const int kr = s * 16 + (lane & 7) + (lane & 8);
                const uint32_t swk = (uint32_t)(kr * 256);
#pragma unroll
                for (int nt = 0; nt < 2; nt++) {
                    int un = (n_warp >> 3) + nt * 2 + (lane >> 4);
                    uint32_t sw = swk + (uint32_t)((((un & 8) | ((un ^ kr) & 7)) << 4));
                    ldsm_x4t(bfr[nt][0], bfr[nt][1], bfr[nt][2], bfr[nt][3], bb + 32768 + sw);
                }
            }
            const int ar = m_warp + (lane & 15);
            const int au = s * 2 + (lane >> 4);
            uint32_t afA[8], afB[8];
            {
                const int r = ar;
                uint32_t sw = (uint32_t)(r * 128 + ((au ^ (r & 7)) << 4));
                ldsm_x4(afA[0], afA[1], afA[2], afA[3], bb + sw);
                ldsm_x4(afA[4], afA[5], afA[6], afA[7], bb + 16384 + sw);
            }
#pragma unroll
            for (int mt = 0; mt < 4; mt++) {
                uint32_t* cur = (mt & 1) ? afB : afA;
                uint32_t* nxt = (mt & 1) ? afA : afB;
                if (mt < 3) {
                    const int r = ar + (mt + 1) * 16;
                    uint32_t sw = (uint32_t)(r * 128 + ((au ^ (r & 7)) << 4));
                    ldsm_x4(nxt[0], nxt[1], nxt[2], nxt[3], bb + sw);
                    ldsm_x4(nxt[4], nxt[5], nxt[6], nxt[7], bb + 16384 + sw);
                }
#pragma unroll
                for (int nb = 0; nb < 4; nb++) {
                    const int nt = nb >> 1, hf = (nb & 1) * 2;
                    mma_f16(acc[mt][nb], cur[0], cur[1], cur[2], cur[3], bfr[nt][hf], bfr[nt][hf + 1]);
                    mma_f16(acc[mt][nb], cur[4], cur[5], cur[6], cur[7], bfr[nt][hf], bfr[nt][hf + 1]);
                }
            }
        }
        __syncthreads();
    }

#pragma unroll
    for (int mt = 0; mt < 4; mt++) {
        const int r0 = m0 + m_warp + mt * 16 + gid;
#pragma unroll
        for (int j = 0; j < 4; j++) {
            const int col = n0 + n_warp + j * 8 + tig * 2;
            float2 bv = *(const float2*)&bias[col];
            float v[4];
            v[0] = acc[mt][j][0] + bv.x; v[1] = acc[mt][j][1] + bv.y;
            v[2] = acc[mt][j][2] + bv.x; v[3] = acc[mt][j][3] + bv.y;
            if (MODE == 0) {
#pragma unroll
                for (int q = 0; q < 4; q++)
                    v[q] = 0.5f * v[q] * (1.0f + erff(v[q] * 0.70710678118654752f));
#pragma unroll
                for (int hp = 0; hp < 2; hp++) {
                    const int rr = r0 + hp * 8;
                    float a = v[hp * 2], b = v[hp * 2 + 1];
                    __half h0 = __float2half_rn(a);
                    __half h1 = __float2half_rn(b);
                    __half l0 = __float2half_rn(a - __half2float(h0));
                    __half l1 = __float2half_rn(b - __half2float(h1));
                    uint32_t ph = (uint32_t)__half_as_ushort(h0) | ((uint32_t)__half_as_ushort(h1) << 16);
                    uint32_t pl = (uint32_t)__half_as_ushort(l0) | ((uint32_t)__half_as_ushort(l1) << 16);
                    *(uint32_t*)(outH + (size_t)rr * Ntot + col) = ph;
                    *(uint32_t*)(outL + (size_t)rr * Ntot + col) = pl;
                }
            } else {
                *(float2*)(outF + (size_t)r0 * Ntot + col) = make_float2(v[0], v[1]);
                *(float2*)(outF + (size_t)(r0 + 8) * Ntot + col) = make_float2(v[2], v[3]);
            }
        }
    }
}

// ---------------------------------------------------------------------------
// c[b,n,i] = sum_j hcm[b,n,(i+j)%H] * Wa[j]
// ---------------------------------------------------------------------------
__global__ void compute_c_kernel(const float* __restrict__ hcm,
                                 const float* __restrict__ Wa,
                                 float* __restrict__ c) {
    __shared__ __align__(16) float hs[1024];
    __shared__ __align__(16) float was[512];
    const int bn = blockIdx.x;
    const int t = threadIdx.x;
#pragma unroll
    for (int r = 0; r < 4; r++) {
        int j = t + 128 * r;
        float v = hcm[(size_t)bn * H_ + j];
        hs[j] = v; hs[j + 512] = v;
        was[j] = Wa[j];
    }
    __syncthreads();
    const int h0 = 4 * t;
    float4 a = {0.f, 0.f, 0.f, 0.f};
    float4 mw = *(const float4*)&hs[h0];
#pragma unroll 4
    for (int i = 0; i < 512; i += 4) {
        float4 kv = *(const float4*)&was[i];
        float4 mn = *(const float4*)&hs[i + 4 + h0];
        a.x = fmaf(kv.x, mw.x, a.x); a.y = fmaf(kv.x, mw.y, a.y); a.z = fmaf(kv.x, mw.z, a.z); a.w = fmaf(kv.x, mw.w, a.w);
        a.x = fmaf(kv.y, mw.y, a.x); a.y = fmaf(kv.y, mw.z, a.y); a.z = fmaf(kv.y, mw.w, a.z); a.w = fmaf(kv.y, mn.x, a.w);
        a.x = fmaf(kv.z, mw.z, a.x); a.y = fmaf(kv.z, mw.w, a.y); a.z = fmaf(kv.z, mn.x, a.z); a.w = fmaf(kv.z, mn.y, a.w);
        a.x = fmaf(kv.w, mw.w, a.x); a.y = fmaf(kv.w, mn.x, a.y); a.z = fmaf(kv.w, mn.y, a.z); a.w = fmaf(kv.w, mn.z, a.w);
        mw = mn;
    }
    *(float4*)&c[(size_t)bn * H_ + h0] = a;
}

// ---------------------------------------------------------------------------
// Kernel S: normalize keys (in place) + scores + softmax -> w[4096,32]
// 512 blocks x 8 rows, 256 threads, ~17.6KB smem (high occupancy).
// c read from L2 with 8-lane coalesced float4 pattern (c4 in [0,128)).
// ---------------------------------------------------------------------------
__global__ void __launch_bounds__(256)
score_softmax2(float* __restrict__ keys, const float* __restrict__ c,
               float* __restrict__ wout) {
    __shared__ __align__(16) float ks[8 * 516];
    __shared__ float sc[8 * 33];
    const int row0 = blockIdx.x * 8;
    const int b = row0 >> 10;
    const int t = threadIdx.x;
    const int lane = t & 31, wid = t >> 5;

    // normalize: warp wid handles row wid
    {
        const int r = wid;
        float4* kg = (float4*)(keys + (size_t)(row0 + r) * H_);
        float4 kv[4];
        float ss = 0.f;
#pragma unroll
        for (int u = 0; u < 4; u++) {
            kv[u] = kg[u * 32 + lane];
            ss += kv[u].x * kv[u].x + kv[u].y * kv[u].y + kv[u].z * kv[u].z + kv[u].w * kv[u].w;
        }
#pragma unroll
        for (int o = 16; o; o >>= 1) ss += __shfl_xor_sync(0xffffffffu, ss, o);
        const float inv = 1.0f / fmaxf(sqrtf(ss), 1e-12f);
#pragma unroll
        for (int u = 0; u < 4; u++) {
            kv[u].x *= inv; kv[u].y *= inv; kv[u].z *= inv; kv[u].w *= inv;
            kg[u * 32 + lane] = kv[u];
            *(float4*)&ks[r * 516 + 4 * (u * 32 + lane)] = kv[u];
        }
    }
    __syncthreads();

    // scores: thread (n = t>>3, l = t&7), float4 cols c4 = l + 8i, i in [0,16)
    {
        const int n = t >> 3, l = t & 7;
        const float4* cb = (const float4*)(c + ((size_t)(b * N_ + n)) * H_);
        float p[8] = {};
#pragma unroll
        for (int i = 0; i < 16; i++) {
            const int c4 = l + 8 * i;       // float4 index, 0..127
            float4 cv = cb[c4];
#pragma unroll
            for (int r = 0; r < 8; r++) {
                float4 kv = *(const float4*)&ks[r * 516 + 4 * c4];
                p[r] += cv.x * kv.x + cv.y * kv.y + cv.z * kv.z + cv.w * kv.w;
            }
        }
#pragma unroll
        for (int o = 1; o < 8; o <<= 1)
#pragma unroll
            for (int r = 0; r < 8; r++)
                p[r] += __shfl_xor_sync(0xffffffffu, p[r], o);
        if (l == 0)
#pragma unroll
            for (int r = 0; r < 8; r++) sc[r * 33 + n] = p[r];
    }
    __syncthreads();

    // softmax: warp wid handles row wid, lanes = slots
    {
        const int r = wid;
        float v = sc[r * 33 + lane];
        float mx = v;
#pragma unroll
        for (int o = 16; o; o >>= 1) mx = fmaxf(mx, __shfl_xor_sync(0xffffffffu, mx, o));
        float e = expf(v - mx);
        float s = e;
#pragma unroll
        for (int o = 16; o; o >>= 1) s += __shfl_xor_sync(0xffffffffu, s, o);
        wout[(size_t)(row0 + r) * N_ + lane] = e / s;
    }
}

// ---------------------------------------------------------------------------
// Kernel M: m[row,:] = sum_n w[row,n] * hcm[b,n,:]
// grid 256 = 128 row-groups x 2 column halves; smem 36KB -> high occupancy.
// ---------------------------------------------------------------------------
__global__ void __launch_bounds__(256)
mixture2(const float* __restrict__ w, const float* __restrict__ hcm,
         float* __restrict__ m) {
    __shared__ __align__(16) float hs[32 * 256];
    __shared__ float ws[32 * 33];
    const int bid = blockIdx.x;
    const int row0 = (bid >> 1) * 32;
    const int half = bid & 1;
    const int b = row0 >> 10;
    const int t = threadIdx.x;
    const int lane = t & 31;

    {
        for (int j = t; j < 32 * 64; j += 256) {
            int n = j >> 6, u = j & 63;
            ((float4*)hs)[n * 64 + u] =
                ((const float4*)(hcm + ((size_t)(b * N_ + n)) * H_ + half * 256))[u];
        }
        float4 wv = ((const float4*)(w + (size_t)row0 * N_))[t];
        int r = t >> 3, n0 = (t & 7) * 4;
        ws[r * 33 + n0 + 0] = wv.x; ws[r * 33 + n0 + 1] = wv.y;
        ws[r * 33 + n0 + 2] = wv.z; ws[r * 33 + n0 + 3] = wv.w;
    }
    __syncthreads();

    {
        const int seg = t >> 5;
        u64 acc[16];
#pragma unroll
        for (int q = 0; q < 16; q++) acc[q] = 0;
        const u64* hp = (const u64*)hs;
#pragma unroll 4
        for (int n = 0; n < 32; n++) {
            u64 w2 = dup2(ws[lane * 33 + n]);
            const ulonglong2* h2 = (const ulonglong2*)(hp + n * 128 + seg * 16);
#pragma unroll
            for (int q = 0; q < 8; q++) {
                ulonglong2 hv = h2[q];
                acc[2 * q] = f2fma(acc[2 * q], w2, hv.x);
                acc[2 * q + 1] = f2fma(acc[2 * q + 1], w2, hv.y);
            }
        }
        u64* mr = (u64*)(m + (size_t)(row0 + lane) * H_ + half * 256 + seg * 32);
#pragma unroll
        for (int q = 0; q < 16; q++) mr[q] = acc[q];
    }
}

// ---------------------------------------------------------------------------
// Kernel C: circular correlation via FFMA2, 8 outputs/thread, swizzled mm2.
// ---------------------------------------------------------------------------
__device__ __forceinline__ void mm_store(float* base, int x, int comp, float v) {
    int p = x >> 1;
    int q = p ^ ((p >> 3) & 7);
    base[q * 4 + (x & 1) * 2 + comp] = v;
}

__global__ void __launch_bounds__(128)
correlate_kernel(const float* __restrict__ keys, const float* __restrict__ m,
                 float* __restrict__ context) {
    __shared__ __align__(16) float k2f[2][512];
    __shared__ __align__(16) float mmf[2][1536];
    const int t = threadIdx.x;
    const int rr = t >> 6, tt = t & 63;
    const int row = blockIdx.x * 2 + rr;

    float* k2r = k2f[rr];
    float* mmr = mmf[rr];
    {
        const float4* kg = (const float4*)(keys + (size_t)row * H_);
        const float4* mg = (const float4*)(m + (size_t)row * H_);
#pragma unroll
        for (int e = 0; e < 2; e++) {
            int j4 = 2 * tt + e;
            float4 kv = kg[j4];
            float4 mv = mg[j4];
            float kvv[4] = {kv.x, kv.y, kv.z, kv.w};
            float mvv[4] = {mv.x, mv.y, mv.z, mv.w};
#pragma unroll
            for (int q = 0; q < 4; q++) {
                int j = 4 * j4 + q;
                if (j < 256) k2r[2 * j] = kvv[q];
                else         k2r[2 * (j - 256) + 1] = kvv[q];
                mm_store(mmr, j, 0, mvv[q]);
                mm_store(mmr, j + 256, 1, mvv[q]);
                if (j < 256) mm_store(mmr, j + 512, 0, mvv[q]);
                else         mm_store(mmr, j - 256, 1, mvv[q]);
            }
        }
    }
    __syncthreads();

    const u64* mp64 = (const u64*)mmr;
    const ulonglong2* kp = (const ulonglong2*)k2r;
    u64 A[8];
    u64 w[8];
#pragma unroll
    for (int q = 0; q < 8; q++) A[q] = 0;
#pragma unroll
    for (int e = 0; e < 4; e++) {
        int u = 4 * tt + e;
        int q = u ^ ((u >> 3) & 7);
        ulonglong2 xv = *(const ulonglong2*)(mp64 + 2 * q);
        w[2 * e] = xv.x; w[2 * e + 1] = xv.y;
    }

#pragma unroll 8
    for (int n = 0; n < 64; n++) {
        ulonglong2 ka = kp[2 * n];
        ulonglong2 kb = kp[2 * n + 1];
        int ua = 4 * tt + 2 * n + 4;
        int ub = ua + 1;
        int pa = ua ^ ((ua >> 3) & 7);
        int pb = ub ^ ((ub >> 3) & 7);
        ulonglong2 xa = *(const ulonglong2*)(mp64 + 2 * pa);
        ulonglong2 xb = *(const ulonglong2*)(mp64 + 2 * pb);
        u64 W8 = xa.x, W9 = xa.y, W10 = xb.x, W11 = xb.y;
        A[0] = f2fma(A[0], ka.x, w[0]); A[1] = f2fma(A[1], ka.x, w[1]);
        A[2] = f2fma(A[2], ka.x, w[2]); A[3] = f2fma(A[3], ka.x, w[3]);
        A[4] = f2fma(A[4], ka.x, w[4]); A[5] = f2fma(A[5], ka.x, w[5]);
        A[6] = f2fma(A[6], ka.x, w[6]); A[7] = f2fma(A[7], ka.x, w[7]);
        A[0] = f2fma(A[0], ka.y, w[1]); A[1] = f2fma(A[1], ka.y, w[2]);
        A[2] = f2fma(A[2], ka.y, w[3]); A[3] = f2fma(A[3], ka.y, w[4]);
        A[4] = f2fma(A[4], ka.y, w[5]); A[5] = f2fma(A[5], ka.y, w[6]);
        A[6] = f2fma(A[6], ka.y, w[7]); A[7] = f2fma(A[7], ka.y, W8);
        A[0] = f2fma(A[0], kb.x, w[2]); A[1] = f2fma(A[1], kb.x, w[3]);
        A[2] = f2fma(A[2], kb.x, w[4]); A[3] = f2fma(A[3], kb.x, w[5]);
        A[4] = f2fma(A[4], kb.x, w[6]); A[5] = f2fma(A[5], kb.x, w[7]);
        A[6] = f2fma(A[6], kb.x, W8);   A[7] = f2fma(A[7], kb.x, W9);
        A[0] = f2fma(A[0], kb.y, w[3]); A[1] = f2fma(A[1], kb.y, w[4]);
        A[2] = f2fma(A[2], kb.y, w[5]); A[3] = f2fma(A[3], kb.y, w[6]);
        A[4] = f2fma(A[4], kb.y, w[7]); A[5] = f2fma(A[5], kb.y, W8);
        A[6] = f2fma(A[6], kb.y, W9);   A[7] = f2fma(A[7], kb.y, W10);
        w[0] = w[4]; w[1] = w[5]; w[2] = w[6]; w[3] = w[7];
        w[4] = W8; w[5] = W9; w[6] = W10; w[7] = W11;
    }

    float o[8];
#pragma unroll
    for (int q = 0; q < 8; q++) {
        float lo, hi;
        unpack2(A[q], lo, hi);
        o[q] = lo + hi;
    }
    float* op = context + (size_t)row * H_ + 8 * tt;
    *(float4*)op = make_float4(o[0], o[1], o[2], o[3]);
    *(float4*)(op + 4) = make_float4(o[4], o[5], o[6], o[7]);
}

// ---------------------------------------------------------------------------
// Launch
// ---------------------------------------------------------------------------
extern "C" void kernel_launch(void* const* d_in, const int* in_sizes, int n_in,
                              void* d_out, int out_size) {
    const float* query = (const float*)d_in[0];
    const float* hcm   = (const float*)d_in[1];
    const float* W1    = (const float*)d_in[2];
    const float* b1    = (const float*)d_in[3];
    const float* W2    = (const float*)d_in[4];
    const float* b2    = (const float*)d_in[5];
    const float* Wa    = (const float*)d_in[6];
    // ba unused: softmax is shift-invariant

    float* out = (float*)d_out;
    float* context = out;
    float* keys    = out + (size_t)M_ * H_;

    __half *qh, *ql, *hh, *hl, *w1f, *w2f;
    float *cbuf, *wbuf, *mbuf;
    cudaGetSymbolAddress((void**)&qh, g_qh);
    cudaGetSymbolAddress((void**)&ql, g_ql);
    cudaGetSymbolAddress((void**)&hh, g_hh);
    cudaGetSymbolAddress((void**)&hl, g_hl);
    cudaGetSymbolAddress((void**)&w1f, g_w1f);
    cudaGetSymbolAddress((void**)&w2f, g_w2f);
    cudaGetSymbolAddress((void**)&cbuf, g_c);
    cudaGetSymbolAddress((void**)&wbuf, g_w);
    cudaGetSymbolAddress((void**)&mbuf, g_m);

    const int GEMM_SMEM = 2 * 49152;   // 96 KB -> 2 CTAs/SM
    cudaFuncSetAttribute(gemm_mma<0>, cudaFuncAttributeMaxDynamicSharedMemorySize, GEMM_SMEM);
    cudaFuncSetAttribute(gemm_mma<1>, cudaFuncAttributeMaxDynamicSharedMemorySize, GEMM_SMEM);

    prep_convert<<<5632, 256>>>(query, W1, W2, qh, ql, w1f, w2f);
    compute_c_kernel<<<B_ * N_, 128>>>(hcm, Wa, cbuf);

    gemm_mma<0><<<dim3(H2_ / 128, M_ / 128), 256, GEMM_SMEM>>>(
        qh, ql, w1f, b1, nullptr, hh, hl, H2_, D_);
    gemm_mma<1><<<dim3(H_ / 128, M_ / 128), 256, GEMM_SMEM>>>(
        hh, hl, w2f, b2, keys, nullptr, nullptr, H_, H2_);

    score_softmax2<<<M_ / 8, 256>>>(keys, cbuf, wbuf);
    mixture2<<<(M_ / 32) * 2, 256>>>(wbuf, hcm, mbuf);
    correlate_kernel<<<M_ / 2, 128>>>(keys, mbuf, context);
}